// round 2
// baseline (speedup 1.0000x reference)
#include <cuda_runtime.h>
#include <math.h>

// ---------------------------------------------------------------------------
// ConformerBlock: B=4, T=1024, D=512, H=8, DH=64, W1=32, WB=65, FF=2048,
// CE=1024, KS=31. Output = (out[B,T,D], probs[B,T,H,WB]) concatenated fp32.
// ---------------------------------------------------------------------------

#define CB 4
#define CT 1024
#define CD 512
#define CH 8
#define CDH 64
#define CW1 32
#define CWB 65
#define CFF 2048
#define CCE 1024
#define CKS 31
#define CEPS 1e-5f

#define NTOK (CB * CT)          // 4096 rows

// ------------------------- scratch (device globals) ------------------------
__device__ float g_ln [NTOK * CD];
__device__ float g_ff [NTOK * CFF];
__device__ float g_h  [NTOK * CD];
__device__ float g_h2 [NTOK * CD];
__device__ float g_q  [NTOK * CD];
__device__ float g_k  [NTOK * CD];
__device__ float g_v  [NTOK * CD];
__device__ float g_ce [NTOK * CCE];
__device__ float g_glu[NTOK * CD];
__device__ float g_dw [NTOK * CD];

// ------------------------------- LayerNorm ---------------------------------
// one block per row (512 elems), 128 threads, 4 elems (float4) per thread
__global__ void ln_k(const float* __restrict__ x, const float* __restrict__ g,
                     const float* __restrict__ b, float* __restrict__ y)
{
    int row = blockIdx.x;
    int tid = threadIdx.x;
    const float4* xr = reinterpret_cast<const float4*>(x + (size_t)row * CD);
    float4 v = xr[tid];

    __shared__ float red1[4];
    __shared__ float red2[4];

    float s = v.x + v.y + v.z + v.w;
    #pragma unroll
    for (int o = 16; o; o >>= 1) s += __shfl_xor_sync(0xffffffffu, s, o);
    if ((tid & 31) == 0) red1[tid >> 5] = s;
    __syncthreads();
    float mean = (red1[0] + red1[1] + red1[2] + red1[3]) * (1.0f / CD);

    float dx = v.x - mean, dy = v.y - mean, dz = v.z - mean, dw = v.w - mean;
    float ss = dx * dx + dy * dy + dz * dz + dw * dw;
    #pragma unroll
    for (int o = 16; o; o >>= 1) ss += __shfl_xor_sync(0xffffffffu, ss, o);
    if ((tid & 31) == 0) red2[tid >> 5] = ss;
    __syncthreads();
    float var = (red2[0] + red2[1] + red2[2] + red2[3]) * (1.0f / CD);
    float inv = rsqrtf(var + CEPS);

    float4 gv = reinterpret_cast<const float4*>(g)[tid];
    float4 bv = reinterpret_cast<const float4*>(b)[tid];
    float4 o4;
    o4.x = dx * inv * gv.x + bv.x;
    o4.y = dy * inv * gv.y + bv.y;
    o4.z = dz * inv * gv.z + bv.z;
    o4.w = dw * inv * gv.w + bv.w;
    reinterpret_cast<float4*>(y + (size_t)row * CD)[tid] = o4;
}

// --------------------------------- GEMM ------------------------------------
// C[M,N] = epilogue(A[M,K] @ B[K,N] + bias)
// MODE: 0 = bias, 1 = swish(bias), 2 = 0.125*(..+bias) (q-scale),
//       3 = res + (..), 4 = res + 0.5*(..)
// 128x128 block tile, BK=16, 256 threads, 8x8 per thread.
template<int MODE>
__global__ __launch_bounds__(256, 2)
void gemm_k(const float* __restrict__ A, const float* __restrict__ Bm,
            const float* __restrict__ bias, const float* __restrict__ res,
            float* __restrict__ C, int M, int N, int K)
{
    __shared__ float As[16][132];   // [k][m], padded: row stride 528B = 16B aligned
    __shared__ float Bs[16][128];   // [k][n]

    const int tid = threadIdx.x;
    const int m0 = blockIdx.y * 128;
    const int n0 = blockIdx.x * 128;
    const int tx = tid & 15;        // 16 col groups
    const int ty = tid >> 4;        // 16 row groups

    float acc[8][8];
    #pragma unroll
    for (int i = 0; i < 8; i++)
        #pragma unroll
        for (int j = 0; j < 8; j++) acc[i][j] = 0.0f;

    for (int k0 = 0; k0 < K; k0 += 16) {
        // A tile: 128 rows x 16 cols, coalesced float4, transpose into As[k][m]
        #pragma unroll
        for (int it = 0; it < 2; it++) {
            int idx = tid + it * 256;
            int row = idx >> 2;          // 0..127
            int c4  = idx & 3;           // 0..3
            float4 v = *reinterpret_cast<const float4*>(
                &A[(size_t)(m0 + row) * K + k0 + c4 * 4]);
            As[c4 * 4 + 0][row] = v.x;
            As[c4 * 4 + 1][row] = v.y;
            As[c4 * 4 + 2][row] = v.z;
            As[c4 * 4 + 3][row] = v.w;
        }
        // B tile: 16 rows x 128 cols, coalesced float4
        #pragma unroll
        for (int it = 0; it < 2; it++) {
            int idx = tid + it * 256;
            int row = idx >> 5;          // 0..15
            int c4  = idx & 31;          // 0..31
            *reinterpret_cast<float4*>(&Bs[row][c4 * 4]) =
                *reinterpret_cast<const float4*>(
                    &Bm[(size_t)(k0 + row) * N + n0 + c4 * 4]);
        }
        __syncthreads();

        #pragma unroll
        for (int k = 0; k < 16; k++) {
            float a[8], b[8];
            float4 a0 = *reinterpret_cast<const float4*>(&As[k][ty * 8]);
            float4 a1 = *reinterpret_cast<const float4*>(&As[k][ty * 8 + 4]);
            a[0] = a0.x; a[1] = a0.y; a[2] = a0.z; a[3] = a0.w;
            a[4] = a1.x; a[5] = a1.y; a[6] = a1.z; a[7] = a1.w;
            float4 b0 = *reinterpret_cast<const float4*>(&Bs[k][tx * 8]);
            float4 b1 = *reinterpret_cast<const float4*>(&Bs[k][tx * 8 + 4]);
            b[0] = b0.x; b[1] = b0.y; b[2] = b0.z; b[3] = b0.w;
            b[4] = b1.x; b[5] = b1.y; b[6] = b1.z; b[7] = b1.w;
            #pragma unroll
            for (int i = 0; i < 8; i++)
                #pragma unroll
                for (int j = 0; j < 8; j++)
                    acc[i][j] = fmaf(a[i], b[j], acc[i][j]);
        }
        __syncthreads();
    }

    #pragma unroll
    for (int i = 0; i < 8; i++) {
        int row = m0 + ty * 8 + i;
        #pragma unroll
        for (int j = 0; j < 8; j++) {
            int col = n0 + tx * 8 + j;
            float c = acc[i][j] + bias[col];
            if (MODE == 1)      c = c / (1.0f + expf(-c));               // swish
            else if (MODE == 2) c *= 0.125f;                             // 1/sqrt(64)
            else if (MODE == 3) c += res[(size_t)row * N + col];
            else if (MODE == 4) c = res[(size_t)row * N + col] + 0.5f * c;
            C[(size_t)row * N + col] = c;
        }
    }
}

// ------------------------------- Attention ---------------------------------
// banded attention: one warp per (b, t, head). Writes probs to d_out slice and
// fuses hout = hin + ctx.
__global__ void attn_k(const float* __restrict__ q, const float* __restrict__ k,
                       const float* __restrict__ v, const float* __restrict__ hin,
                       float* __restrict__ hout, float* __restrict__ probs)
{
    __shared__ float sc[4][CWB + 1];
    int warp = threadIdx.x >> 5;
    int lane = threadIdx.x & 31;
    int item = blockIdx.x * 4 + warp;          // < B*T*H
    int head = item & (CH - 1);
    int bt   = item >> 3;                      // b*T + t
    int t    = bt & (CT - 1);
    int brow = bt - t;                         // b*T

    const float2* qrow = reinterpret_cast<const float2*>(q + (size_t)bt * CD + head * CDH);
    float2 q2 = qrow[lane];

    // scores (q already scaled by 1/sqrt(DH))
    for (int w = 0; w < CWB; w++) {
        int tk = t + w - CW1;
        float val = -1e9f;
        if (tk >= 0 && tk < CT) {
            const float2* krow =
                reinterpret_cast<const float2*>(k + (size_t)(brow + tk) * CD + head * CDH);
            float2 k2 = krow[lane];
            float p = q2.x * k2.x + q2.y * k2.y;
            #pragma unroll
            for (int o = 16; o; o >>= 1) p += __shfl_xor_sync(0xffffffffu, p, o);
            val = p;
        }
        if (lane == 0) sc[warp][w] = val;
    }
    __syncwarp();

    // softmax over the 65 window slots
    float m = -1e30f;
    for (int w = lane; w < CWB; w += 32) m = fmaxf(m, sc[warp][w]);
    #pragma unroll
    for (int o = 16; o; o >>= 1) m = fmaxf(m, __shfl_xor_sync(0xffffffffu, m, o));
    float ssum = 0.0f;
    for (int w = lane; w < CWB; w += 32) {
        float e = expf(sc[warp][w] - m);
        sc[warp][w] = e;
        ssum += e;
    }
    #pragma unroll
    for (int o = 16; o; o >>= 1) ssum += __shfl_xor_sync(0xffffffffu, ssum, o);
    float inv = 1.0f / ssum;
    __syncwarp();

    float* prow = probs + (size_t)item * CWB;
    for (int w = lane; w < CWB; w += 32) {
        float p = sc[warp][w] * inv;
        sc[warp][w] = p;
        prow[w] = p;
    }
    __syncwarp();

    // ctx accumulation, 2 dims per lane
    float cx = 0.0f, cy = 0.0f;
    for (int w = 0; w < CWB; w++) {
        int tk = t + w - CW1;
        if (tk < 0 || tk >= CT) continue;
        float p = sc[warp][w];
        const float2* vrow =
            reinterpret_cast<const float2*>(v + (size_t)(brow + tk) * CD + head * CDH);
        float2 v2 = vrow[lane];
        cx = fmaf(p, v2.x, cx);
        cy = fmaf(p, v2.y, cy);
    }
    size_t off = (size_t)bt * CD + head * CDH + lane * 2;
    hout[off]     = hin[off]     + cx;
    hout[off + 1] = hin[off + 1] + cy;
}

// ---------------------------------- GLU ------------------------------------
__global__ void glu_k(const float* __restrict__ in, float* __restrict__ out)
{
    int i = blockIdx.x * 256 + threadIdx.x;    // NTOK*CD threads
    int row = i >> 9;
    int col = i & (CD - 1);
    float a = in[(size_t)row * CCE + col];
    float g = in[(size_t)row * CCE + CD + col];
    out[i] = a / (1.0f + expf(-g));
}

// -------------------- depthwise conv + BN + swish ---------------------------
// grid: (B*T, D/128), 128 threads (one channel each)
__global__ void dwconv_k(const float* __restrict__ in, const float* __restrict__ w,
                         const float* __restrict__ dwb, const float* __restrict__ bng,
                         const float* __restrict__ bnb, float* __restrict__ out)
{
    int c  = blockIdx.y * 128 + threadIdx.x;
    int bt = blockIdx.x;
    int t  = bt & (CT - 1);
    int brow = bt - t;

    float acc = 0.0f;
    #pragma unroll
    for (int kk = 0; kk < CKS; kk++) {
        int tt = t + kk - (CKS - 1) / 2;
        if (tt >= 0 && tt < CT)
            acc = fmaf(__ldg(&w[kk * CD + c]),
                       __ldg(&in[(size_t)(brow + tt) * CD + c]), acc);
    }
    acc += dwb[c];
    acc = acc * (rsqrtf(1.0f + CEPS) * bng[c]) + bnb[c];
    out[(size_t)bt * CD + c] = acc / (1.0f + expf(-acc));   // swish
}

// ------------------------------ launch -------------------------------------
extern "C" void kernel_launch(void* const* d_in, const int* in_sizes, int n_in,
                              void* d_out, int out_size)
{
    (void)in_sizes; (void)n_in; (void)out_size;
    const float* x          = (const float*)d_in[0];
    const float* ff1_ln_g   = (const float*)d_in[1];
    const float* ff1_ln_b   = (const float*)d_in[2];
    const float* ff1_w1     = (const float*)d_in[3];
    const float* ff1_b1     = (const float*)d_in[4];
    const float* ff1_w2     = (const float*)d_in[5];
    const float* ff1_b2     = (const float*)d_in[6];
    const float* ff2_ln_g   = (const float*)d_in[7];
    const float* ff2_ln_b   = (const float*)d_in[8];
    const float* ff2_w1     = (const float*)d_in[9];
    const float* ff2_b1     = (const float*)d_in[10];
    const float* ff2_w2     = (const float*)d_in[11];
    const float* ff2_b2     = (const float*)d_in[12];
    const float* wq         = (const float*)d_in[13];
    const float* bq         = (const float*)d_in[14];
    const float* wk         = (const float*)d_in[15];
    const float* bk         = (const float*)d_in[16];
    const float* wv         = (const float*)d_in[17];
    const float* bv         = (const float*)d_in[18];
    const float* conv_ln_g  = (const float*)d_in[19];
    const float* conv_ln_b  = (const float*)d_in[20];
    const float* conv_pw1_w = (const float*)d_in[21];
    const float* conv_pw1_b = (const float*)d_in[22];
    const float* conv_dw_w  = (const float*)d_in[23];
    const float* conv_dw_b  = (const float*)d_in[24];
    const float* conv_bn_g  = (const float*)d_in[25];
    const float* conv_bn_b  = (const float*)d_in[26];
    const float* conv_pw2_w = (const float*)d_in[27];
    const float* conv_pw2_b = (const float*)d_in[28];
    const float* final_ln_g = (const float*)d_in[29];
    const float* final_ln_b = (const float*)d_in[30];

    float* out_main  = (float*)d_out;                         // (B,T,D)
    float* out_probs = (float*)d_out + (size_t)NTOK * CD;     // (B,T,H,WB)

    float *ln_, *ff_, *h_, *h2_, *q_, *k_, *v_, *ce_, *glu_, *dw_;
    cudaGetSymbolAddress((void**)&ln_,  g_ln);
    cudaGetSymbolAddress((void**)&ff_,  g_ff);
    cudaGetSymbolAddress((void**)&h_,   g_h);
    cudaGetSymbolAddress((void**)&h2_,  g_h2);
    cudaGetSymbolAddress((void**)&q_,   g_q);
    cudaGetSymbolAddress((void**)&k_,   g_k);
    cudaGetSymbolAddress((void**)&v_,   g_v);
    cudaGetSymbolAddress((void**)&ce_,  g_ce);
    cudaGetSymbolAddress((void**)&glu_, g_glu);
    cudaGetSymbolAddress((void**)&dw_,  g_dw);

    dim3 blk256(256);
    dim3 gFF1(CFF / 128, NTOK / 128);   // N=2048
    dim3 gD  (CD  / 128, NTOK / 128);   // N=512
    dim3 gCE (CCE / 128, NTOK / 128);   // N=1024

    // ---- FF1: h = x + 0.5 * ff(x) ----
    ln_k<<<NTOK, 128>>>(x, ff1_ln_g, ff1_ln_b, ln_);
    gemm_k<1><<<gFF1, blk256>>>(ln_, ff1_w1, ff1_b1, nullptr, ff_, NTOK, CFF, CD);
    gemm_k<4><<<gD,   blk256>>>(ff_, ff1_w2, ff1_b2, x,       h_,  NTOK, CD, CFF);

    // ---- QKV ----
    gemm_k<2><<<gD, blk256>>>(h_, wq, bq, nullptr, q_, NTOK, CD, CD);
    gemm_k<0><<<gD, blk256>>>(h_, wk, bk, nullptr, k_, NTOK, CD, CD);
    gemm_k<0><<<gD, blk256>>>(h_, wv, bv, nullptr, v_, NTOK, CD, CD);

    // ---- attention (h2 = h + ctx; probs -> d_out) ----
    attn_k<<<(NTOK * CH) / 4, 128>>>(q_, k_, v_, h_, h2_, out_probs);

    // ---- conv module: h = h2 + conv(h2) ----
    ln_k<<<NTOK, 128>>>(h2_, conv_ln_g, conv_ln_b, ln_);
    gemm_k<0><<<gCE, blk256>>>(ln_, conv_pw1_w, conv_pw1_b, nullptr, ce_, NTOK, CCE, CD);
    glu_k<<<(NTOK * CD) / 256, blk256>>>(ce_, glu_);
    dwconv_k<<<dim3(NTOK, CD / 128), 128>>>(glu_, conv_dw_w, conv_dw_b,
                                            conv_bn_g, conv_bn_b, dw_);
    gemm_k<3><<<gD, blk256>>>(dw_, conv_pw2_w, conv_pw2_b, h2_, h_, NTOK, CD, CD);

    // ---- FF2: h2 = h + 0.5 * ff(h) ----
    ln_k<<<NTOK, 128>>>(h_, ff2_ln_g, ff2_ln_b, ln_);
    gemm_k<1><<<gFF1, blk256>>>(ln_, ff2_w1, ff2_b1, nullptr, ff_, NTOK, CFF, CD);
    gemm_k<4><<<gD,   blk256>>>(ff_, ff2_w2, ff2_b2, h_,      h2_, NTOK, CD, CFF);

    // ---- final LN -> out ----
    ln_k<<<NTOK, 128>>>(h2_, final_ln_g, final_ln_b, out_main);
}

// round 4
// speedup vs baseline: 2.3585x; 2.3585x over previous
#include <cuda_runtime.h>
#include <math.h>
#include <stdint.h>

// ---------------------------------------------------------------------------
// ConformerBlock: B=4, T=1024, D=512, H=8, DH=64, W1=32, WB=65, FF=2048,
// CE=1024, KS=31. Output = (out[B,T,D], probs[B,T,H,WB]) concatenated fp32.
// GEMMs on tensor cores via tf32 mma.sync (RNA-rounded operands).
// ---------------------------------------------------------------------------

#define CB 4
#define CT 1024
#define CD 512
#define CH 8
#define CDH 64
#define CW1 32
#define CWB 65
#define CFF 2048
#define CCE 1024
#define CKS 31
#define CEPS 1e-5f

#define NTOK (CB * CT)          // 4096 rows

// ------------------------- scratch (device globals) ------------------------
__device__ float g_ln [NTOK * CD];
__device__ float g_ff [NTOK * CFF];
__device__ float g_h  [NTOK * CD];
__device__ float g_h2 [NTOK * CD];
__device__ float g_q  [NTOK * CD];
__device__ float g_k  [NTOK * CD];
__device__ float g_v  [NTOK * CD];
__device__ float g_ce [NTOK * CCE];
__device__ float g_glu[NTOK * CD];
__device__ float g_dw [NTOK * CD];

// ------------------------------- LayerNorm ---------------------------------
__global__ void ln_k(const float* __restrict__ x, const float* __restrict__ g,
                     const float* __restrict__ b, float* __restrict__ y)
{
    int row = blockIdx.x;
    int tid = threadIdx.x;
    const float4* xr = reinterpret_cast<const float4*>(x + (size_t)row * CD);
    float4 v = xr[tid];

    __shared__ float red1[4];
    __shared__ float red2[4];

    float s = v.x + v.y + v.z + v.w;
    #pragma unroll
    for (int o = 16; o; o >>= 1) s += __shfl_xor_sync(0xffffffffu, s, o);
    if ((tid & 31) == 0) red1[tid >> 5] = s;
    __syncthreads();
    float mean = (red1[0] + red1[1] + red1[2] + red1[3]) * (1.0f / CD);

    float dx = v.x - mean, dy = v.y - mean, dz = v.z - mean, dw = v.w - mean;
    float ss = dx * dx + dy * dy + dz * dz + dw * dw;
    #pragma unroll
    for (int o = 16; o; o >>= 1) ss += __shfl_xor_sync(0xffffffffu, ss, o);
    if ((tid & 31) == 0) red2[tid >> 5] = ss;
    __syncthreads();
    float var = (red2[0] + red2[1] + red2[2] + red2[3]) * (1.0f / CD);
    float inv = rsqrtf(var + CEPS);

    float4 gv = reinterpret_cast<const float4*>(g)[tid];
    float4 bv = reinterpret_cast<const float4*>(b)[tid];
    float4 o4;
    o4.x = dx * inv * gv.x + bv.x;
    o4.y = dy * inv * gv.y + bv.y;
    o4.z = dz * inv * gv.z + bv.z;
    o4.w = dw * inv * gv.w + bv.w;
    reinterpret_cast<float4*>(y + (size_t)row * CD)[tid] = o4;
}

// ----------------------------- tf32 helpers --------------------------------
__device__ __forceinline__ uint32_t to_tf32(float x)
{
    uint32_t y;
    asm("cvt.rna.tf32.f32 %0, %1;" : "=r"(y) : "f"(x));
    return y;
}

#define MMA_TF32(d, a, b)                                                     \
    asm volatile(                                                             \
        "mma.sync.aligned.m16n8k8.row.col.f32.tf32.tf32.f32 "                 \
        "{%0,%1,%2,%3}, {%4,%5,%6,%7}, {%8,%9}, {%0,%1,%2,%3};"               \
        : "+f"(d[0]), "+f"(d[1]), "+f"(d[2]), "+f"(d[3])                      \
        : "r"(a[0]), "r"(a[1]), "r"(a[2]), "r"(a[3]), "r"(b[0]), "r"(b[1]))

// ------------------------------- TC GEMM ------------------------------------
// C[M,N] = epilogue(A[M,K] @ B[K,N] + bias)
// MODE: 0 = bias, 1 = swish, 2 = 0.125*(..), 3 = res+, 4 = res + 0.5*
// 128x128 block tile, BK=16, 256 threads / 8 warps (2x4), 64x32 warp tiles.
#define AS_STRIDE 20   // [m][k] A tile, pad 16->20: conflict-free frag loads
#define BS_STRIDE 136  // [k][n] B tile, pad 128->136: conflict-free frag loads

template<int MODE>
__global__ __launch_bounds__(256, 2)
void gemm_tc(const float* __restrict__ A, const float* __restrict__ Bm,
             const float* __restrict__ bias, const float* __restrict__ res,
             float* __restrict__ C, int M, int N, int K)
{
    __shared__ uint32_t As[128 * AS_STRIDE];   // A tile [m][k] (tf32 bits)
    __shared__ uint32_t Bs[16 * BS_STRIDE];    // B tile [k][n] (tf32 bits)

    const int tid  = threadIdx.x;
    const int lane = tid & 31;
    const int warp = tid >> 5;
    const int g    = lane >> 2;   // groupID 0..7
    const int tig  = lane & 3;    // thread-in-group 0..3

    const int m0 = blockIdx.y * 128;
    const int n0 = blockIdx.x * 128;
    const int wm = (warp & 1) * 64;    // warp m offset
    const int wn = (warp >> 1) * 32;   // warp n offset

    float acc[4][4][4];
    #pragma unroll
    for (int mt = 0; mt < 4; mt++)
        #pragma unroll
        for (int nt = 0; nt < 4; nt++)
            #pragma unroll
            for (int i = 0; i < 4; i++) acc[mt][nt][i] = 0.0f;

    // load mappings (each thread: 2 float4 of A, 2 float4 of B per k-chunk)
    // A: idx = tid + it*256 in [0,512): row = idx>>2 (0..127), c4 = idx&3
    // B: row = idx>>5 (0..15), c4 = idx&31
    float4 ra[2], rb[2];

    {   // prologue load k0 = 0
        #pragma unroll
        for (int it = 0; it < 2; it++) {
            int idx = tid + it * 256;
            ra[it] = *reinterpret_cast<const float4*>(
                &A[(size_t)(m0 + (idx >> 2)) * K + (idx & 3) * 4]);
            rb[it] = *reinterpret_cast<const float4*>(
                &Bm[(size_t)(idx >> 5) * N + n0 + (idx & 31) * 4]);
        }
    }

    for (int k0 = 0; k0 < K; k0 += 16) {
        __syncthreads();   // previous compute done before overwrite
        #pragma unroll
        for (int it = 0; it < 2; it++) {
            int idx = tid + it * 256;
            // A: [m][k] tile, contiguous 4 k-values
            uint32_t* pa = &As[(idx >> 2) * AS_STRIDE + (idx & 3) * 4];
            pa[0] = to_tf32(ra[it].x); pa[1] = to_tf32(ra[it].y);
            pa[2] = to_tf32(ra[it].z); pa[3] = to_tf32(ra[it].w);
            // B: [k][n] tile
            uint32_t* pb = &Bs[(idx >> 5) * BS_STRIDE + (idx & 31) * 4];
            pb[0] = to_tf32(rb[it].x); pb[1] = to_tf32(rb[it].y);
            pb[2] = to_tf32(rb[it].z); pb[3] = to_tf32(rb[it].w);
        }
        __syncthreads();

        if (k0 + 16 < K) {   // prefetch next chunk (overlaps with MMAs)
            #pragma unroll
            for (int it = 0; it < 2; it++) {
                int idx = tid + it * 256;
                ra[it] = *reinterpret_cast<const float4*>(
                    &A[(size_t)(m0 + (idx >> 2)) * K + k0 + 16 + (idx & 3) * 4]);
                rb[it] = *reinterpret_cast<const float4*>(
                    &Bm[(size_t)(k0 + 16 + (idx >> 5)) * N + n0 + (idx & 31) * 4]);
            }
        }

        #pragma unroll
        for (int ks = 0; ks < 2; ks++) {
            const int kk = ks * 8;
            uint32_t bfrag[4][2];
            #pragma unroll
            for (int nt = 0; nt < 4; nt++) {
                int col = wn + nt * 8 + g;
                bfrag[nt][0] = Bs[(kk + tig)     * BS_STRIDE + col];
                bfrag[nt][1] = Bs[(kk + tig + 4) * BS_STRIDE + col];
            }
            #pragma unroll
            for (int mt = 0; mt < 4; mt++) {
                uint32_t afrag[4];
                int r0 = wm + mt * 16 + g;
                afrag[0] = As[r0       * AS_STRIDE + kk + tig];
                afrag[1] = As[(r0 + 8) * AS_STRIDE + kk + tig];
                afrag[2] = As[r0       * AS_STRIDE + kk + tig + 4];
                afrag[3] = As[(r0 + 8) * AS_STRIDE + kk + tig + 4];
                #pragma unroll
                for (int nt = 0; nt < 4; nt++)
                    MMA_TF32(acc[mt][nt], afrag, bfrag[nt]);
            }
        }
    }

    // ----------------------------- epilogue ---------------------------------
    #pragma unroll
    for (int mt = 0; mt < 4; mt++) {
        int r0 = m0 + wm + mt * 16 + g;
        #pragma unroll
        for (int nt = 0; nt < 4; nt++) {
            int cb = n0 + wn + nt * 8 + tig * 2;
            float b0 = bias[cb], b1 = bias[cb + 1];
            #pragma unroll
            for (int half = 0; half < 2; half++) {
                int row = r0 + half * 8;
                float c0 = acc[mt][nt][half * 2 + 0] + b0;
                float c1 = acc[mt][nt][half * 2 + 1] + b1;
                if (MODE == 1) {
                    c0 = c0 / (1.0f + expf(-c0));
                    c1 = c1 / (1.0f + expf(-c1));
                } else if (MODE == 2) {
                    c0 *= 0.125f; c1 *= 0.125f;
                } else if (MODE == 3) {
                    const float2 r = *reinterpret_cast<const float2*>(
                        &res[(size_t)row * N + cb]);
                    c0 += r.x; c1 += r.y;
                } else if (MODE == 4) {
                    const float2 r = *reinterpret_cast<const float2*>(
                        &res[(size_t)row * N + cb]);
                    c0 = r.x + 0.5f * c0; c1 = r.y + 0.5f * c1;
                }
                float2 o; o.x = c0; o.y = c1;
                *reinterpret_cast<float2*>(&C[(size_t)row * N + cb]) = o;
            }
        }
    }
}

// ------------------------------- Attention ---------------------------------
__global__ void attn_k(const float* __restrict__ q, const float* __restrict__ k,
                       const float* __restrict__ v, const float* __restrict__ hin,
                       float* __restrict__ hout, float* __restrict__ probs)
{
    __shared__ float sc[4][CWB + 1];
    int warp = threadIdx.x >> 5;
    int lane = threadIdx.x & 31;
    int item = blockIdx.x * 4 + warp;          // < B*T*H
    int head = item & (CH - 1);
    int bt   = item >> 3;                      // b*T + t
    int t    = bt & (CT - 1);
    int brow = bt - t;                         // b*T

    const float2* qrow = reinterpret_cast<const float2*>(q + (size_t)bt * CD + head * CDH);
    float2 q2 = qrow[lane];

    for (int w = 0; w < CWB; w++) {
        int tk = t + w - CW1;
        float val = -1e9f;
        if (tk >= 0 && tk < CT) {
            const float2* krow =
                reinterpret_cast<const float2*>(k + (size_t)(brow + tk) * CD + head * CDH);
            float2 k2 = krow[lane];
            float p = q2.x * k2.x + q2.y * k2.y;
            #pragma unroll
            for (int o = 16; o; o >>= 1) p += __shfl_xor_sync(0xffffffffu, p, o);
            val = p;
        }
        if (lane == 0) sc[warp][w] = val;
    }
    __syncwarp();

    float m = -1e30f;
    for (int w = lane; w < CWB; w += 32) m = fmaxf(m, sc[warp][w]);
    #pragma unroll
    for (int o = 16; o; o >>= 1) m = fmaxf(m, __shfl_xor_sync(0xffffffffu, m, o));
    float ssum = 0.0f;
    for (int w = lane; w < CWB; w += 32) {
        float e = expf(sc[warp][w] - m);
        sc[warp][w] = e;
        ssum += e;
    }
    #pragma unroll
    for (int o = 16; o; o >>= 1) ssum += __shfl_xor_sync(0xffffffffu, ssum, o);
    float inv = 1.0f / ssum;
    __syncwarp();

    float* prow = probs + (size_t)item * CWB;
    for (int w = lane; w < CWB; w += 32) {
        float p = sc[warp][w] * inv;
        sc[warp][w] = p;
        prow[w] = p;
    }
    __syncwarp();

    float cx = 0.0f, cy = 0.0f;
    for (int w = 0; w < CWB; w++) {
        int tk = t + w - CW1;
        if (tk < 0 || tk >= CT) continue;
        float p = sc[warp][w];
        const float2* vrow =
            reinterpret_cast<const float2*>(v + (size_t)(brow + tk) * CD + head * CDH);
        float2 v2 = vrow[lane];
        cx = fmaf(p, v2.x, cx);
        cy = fmaf(p, v2.y, cy);
    }
    size_t off = (size_t)bt * CD + head * CDH + lane * 2;
    hout[off]     = hin[off]     + cx;
    hout[off + 1] = hin[off + 1] + cy;
}

// ---------------------------------- GLU ------------------------------------
__global__ void glu_k(const float* __restrict__ in, float* __restrict__ out)
{
    int i = blockIdx.x * 256 + threadIdx.x;    // NTOK*CD threads
    int row = i >> 9;
    int col = i & (CD - 1);
    float a = in[(size_t)row * CCE + col];
    float g = in[(size_t)row * CCE + CD + col];
    out[i] = a / (1.0f + expf(-g));
}

// -------------------- depthwise conv + BN + swish ---------------------------
__global__ void dwconv_k(const float* __restrict__ in, const float* __restrict__ w,
                         const float* __restrict__ dwb, const float* __restrict__ bng,
                         const float* __restrict__ bnb, float* __restrict__ out)
{
    int c  = blockIdx.y * 128 + threadIdx.x;
    int bt = blockIdx.x;
    int t  = bt & (CT - 1);
    int brow = bt - t;

    float acc = 0.0f;
    #pragma unroll
    for (int kk = 0; kk < CKS; kk++) {
        int tt = t + kk - (CKS - 1) / 2;
        if (tt >= 0 && tt < CT)
            acc = fmaf(__ldg(&w[kk * CD + c]),
                       __ldg(&in[(size_t)(brow + tt) * CD + c]), acc);
    }
    acc += dwb[c];
    acc = acc * (rsqrtf(1.0f + CEPS) * bng[c]) + bnb[c];
    out[(size_t)bt * CD + c] = acc / (1.0f + expf(-acc));   // swish
}

// ------------------------------ launch -------------------------------------
extern "C" void kernel_launch(void* const* d_in, const int* in_sizes, int n_in,
                              void* d_out, int out_size)
{
    (void)in_sizes; (void)n_in; (void)out_size;
    const float* x          = (const float*)d_in[0];
    const float* ff1_ln_g   = (const float*)d_in[1];
    const float* ff1_ln_b   = (const float*)d_in[2];
    const float* ff1_w1     = (const float*)d_in[3];
    const float* ff1_b1     = (const float*)d_in[4];
    const float* ff1_w2     = (const float*)d_in[5];
    const float* ff1_b2     = (const float*)d_in[6];
    const float* ff2_ln_g   = (const float*)d_in[7];
    const float* ff2_ln_b   = (const float*)d_in[8];
    const float* ff2_w1     = (const float*)d_in[9];
    const float* ff2_b1     = (const float*)d_in[10];
    const float* ff2_w2     = (const float*)d_in[11];
    const float* ff2_b2     = (const float*)d_in[12];
    const float* wq         = (const float*)d_in[13];
    const float* bq         = (const float*)d_in[14];
    const float* wk         = (const float*)d_in[15];
    const float* bk         = (const float*)d_in[16];
    const float* wv         = (const float*)d_in[17];
    const float* bv         = (const float*)d_in[18];
    const float* conv_ln_g  = (const float*)d_in[19];
    const float* conv_ln_b  = (const float*)d_in[20];
    const float* conv_pw1_w = (const float*)d_in[21];
    const float* conv_pw1_b = (const float*)d_in[22];
    const float* conv_dw_w  = (const float*)d_in[23];
    const float* conv_dw_b  = (const float*)d_in[24];
    const float* conv_bn_g  = (const float*)d_in[25];
    const float* conv_bn_b  = (const float*)d_in[26];
    const float* conv_pw2_w = (const float*)d_in[27];
    const float* conv_pw2_b = (const float*)d_in[28];
    const float* final_ln_g = (const float*)d_in[29];
    const float* final_ln_b = (const float*)d_in[30];

    float* out_main  = (float*)d_out;                         // (B,T,D)
    float* out_probs = (float*)d_out + (size_t)NTOK * CD;     // (B,T,H,WB)

    float *ln_, *ff_, *h_, *h2_, *q_, *k_, *v_, *ce_, *glu_, *dw_;
    cudaGetSymbolAddress((void**)&ln_,  g_ln);
    cudaGetSymbolAddress((void**)&ff_,  g_ff);
    cudaGetSymbolAddress((void**)&h_,   g_h);
    cudaGetSymbolAddress((void**)&h2_,  g_h2);
    cudaGetSymbolAddress((void**)&q_,   g_q);
    cudaGetSymbolAddress((void**)&k_,   g_k);
    cudaGetSymbolAddress((void**)&v_,   g_v);
    cudaGetSymbolAddress((void**)&ce_,  g_ce);
    cudaGetSymbolAddress((void**)&glu_, g_glu);
    cudaGetSymbolAddress((void**)&dw_,  g_dw);

    dim3 blk256(256);
    dim3 gFF1(CFF / 128, NTOK / 128);   // N=2048
    dim3 gD  (CD  / 128, NTOK / 128);   // N=512
    dim3 gCE (CCE / 128, NTOK / 128);   // N=1024

    // ---- FF1: h = x + 0.5 * ff(x) ----
    ln_k<<<NTOK, 128>>>(x, ff1_ln_g, ff1_ln_b, ln_);
    gemm_tc<1><<<gFF1, blk256>>>(ln_, ff1_w1, ff1_b1, nullptr, ff_, NTOK, CFF, CD);
    gemm_tc<4><<<gD,   blk256>>>(ff_, ff1_w2, ff1_b2, x,       h_,  NTOK, CD, CFF);

    // ---- QKV ----
    gemm_tc<2><<<gD, blk256>>>(h_, wq, bq, nullptr, q_, NTOK, CD, CD);
    gemm_tc<0><<<gD, blk256>>>(h_, wk, bk, nullptr, k_, NTOK, CD, CD);
    gemm_tc<0><<<gD, blk256>>>(h_, wv, bv, nullptr, v_, NTOK, CD, CD);

    // ---- attention (h2 = h + ctx; probs -> d_out) ----
    attn_k<<<(NTOK * CH) / 4, 128>>>(q_, k_, v_, h_, h2_, out_probs);

    // ---- conv module: h = h2 + conv(h2) ----
    ln_k<<<NTOK, 128>>>(h2_, conv_ln_g, conv_ln_b, ln_);
    gemm_tc<0><<<gCE, blk256>>>(ln_, conv_pw1_w, conv_pw1_b, nullptr, ce_, NTOK, CCE, CD);
    glu_k<<<(NTOK * CD) / 256, blk256>>>(ce_, glu_);
    dwconv_k<<<dim3(NTOK, CD / 128), 128>>>(glu_, conv_dw_w, conv_dw_b,
                                            conv_bn_g, conv_bn_b, dw_);
    gemm_tc<3><<<gD, blk256>>>(dw_, conv_pw2_w, conv_pw2_b, h2_, h_, NTOK, CD, CD);

    // ---- FF2: h2 = h + 0.5 * ff(h) ----
    ln_k<<<NTOK, 128>>>(h_, ff2_ln_g, ff2_ln_b, ln_);
    gemm_tc<1><<<gFF1, blk256>>>(ln_, ff2_w1, ff2_b1, nullptr, ff_, NTOK, CFF, CD);
    gemm_tc<4><<<gD,   blk256>>>(ff_, ff2_w2, ff2_b2, h_,      h2_, NTOK, CD, CFF);

    // ---- final LN -> out ----
    ln_k<<<NTOK, 128>>>(h2_, final_ln_g, final_ln_b, out_main);
}

// round 5
// speedup vs baseline: 2.4610x; 1.0435x over previous
#include <cuda_runtime.h>
#include <math.h>
#include <stdint.h>

// ---------------------------------------------------------------------------
// ConformerBlock: B=4, T=1024, D=512, H=8, DH=64, W1=32, WB=65, FF=2048,
// CE=1024, KS=31. Output = (out[B,T,D], probs[B,T,H,WB]) concatenated fp32.
// GEMMs: tf32 mma.sync, cp.async 2-stage pipeline, consumer-side RNA cvt.
// ---------------------------------------------------------------------------

#define CB 4
#define CT 1024
#define CD 512
#define CH 8
#define CDH 64
#define CW1 32
#define CWB 65
#define CFF 2048
#define CCE 1024
#define CKS 31
#define CEPS 1e-5f

#define NTOK (CB * CT)          // 4096 rows

// ------------------------- scratch (device globals) ------------------------
__device__ float g_ln [NTOK * CD];
__device__ float g_ff [NTOK * CFF];
__device__ float g_h  [NTOK * CD];
__device__ float g_h2 [NTOK * CD];
__device__ float g_q  [NTOK * CD];
__device__ float g_k  [NTOK * CD];
__device__ float g_v  [NTOK * CD];
__device__ float g_ce [NTOK * CCE];
__device__ float g_glu[NTOK * CD];
__device__ float g_dw [NTOK * CD];

// ------------------------------- LayerNorm ---------------------------------
__global__ void ln_k(const float* __restrict__ x, const float* __restrict__ g,
                     const float* __restrict__ b, float* __restrict__ y)
{
    int row = blockIdx.x;
    int tid = threadIdx.x;
    const float4* xr = reinterpret_cast<const float4*>(x + (size_t)row * CD);
    float4 v = xr[tid];

    __shared__ float red1[4];
    __shared__ float red2[4];

    float s = v.x + v.y + v.z + v.w;
    #pragma unroll
    for (int o = 16; o; o >>= 1) s += __shfl_xor_sync(0xffffffffu, s, o);
    if ((tid & 31) == 0) red1[tid >> 5] = s;
    __syncthreads();
    float mean = (red1[0] + red1[1] + red1[2] + red1[3]) * (1.0f / CD);

    float dx = v.x - mean, dy = v.y - mean, dz = v.z - mean, dw = v.w - mean;
    float ss = dx * dx + dy * dy + dz * dz + dw * dw;
    #pragma unroll
    for (int o = 16; o; o >>= 1) ss += __shfl_xor_sync(0xffffffffu, ss, o);
    if ((tid & 31) == 0) red2[tid >> 5] = ss;
    __syncthreads();
    float var = (red2[0] + red2[1] + red2[2] + red2[3]) * (1.0f / CD);
    float inv = rsqrtf(var + CEPS);

    float4 gv = reinterpret_cast<const float4*>(g)[tid];
    float4 bv = reinterpret_cast<const float4*>(b)[tid];
    float4 o4;
    o4.x = dx * inv * gv.x + bv.x;
    o4.y = dy * inv * gv.y + bv.y;
    o4.z = dz * inv * gv.z + bv.z;
    o4.w = dw * inv * gv.w + bv.w;
    reinterpret_cast<float4*>(y + (size_t)row * CD)[tid] = o4;
}

// ----------------------------- tf32 / async helpers ------------------------
__device__ __forceinline__ uint32_t to_tf32(float x)
{
    uint32_t y;
    asm("cvt.rna.tf32.f32 %0, %1;" : "=r"(y) : "f"(x));
    return y;
}

__device__ __forceinline__ void cp16(void* smem_dst, const void* gsrc)
{
    uint32_t s = (uint32_t)__cvta_generic_to_shared(smem_dst);
    asm volatile("cp.async.cg.shared.global [%0], [%1], 16;\n" :: "r"(s), "l"(gsrc));
}

#define MMA_TF32(d, a, b)                                                     \
    asm volatile(                                                             \
        "mma.sync.aligned.m16n8k8.row.col.f32.tf32.tf32.f32 "                 \
        "{%0,%1,%2,%3}, {%4,%5,%6,%7}, {%8,%9}, {%0,%1,%2,%3};"               \
        : "+f"(d[0]), "+f"(d[1]), "+f"(d[2]), "+f"(d[3])                      \
        : "r"(a[0]), "r"(a[1]), "r"(a[2]), "r"(b[0]), "r"(b[1]), "r"(a[3]))

// NOTE: operand order fixed below (a[3] must be 4th A register) — use explicit
// form instead to avoid any confusion:
#undef MMA_TF32
#define MMA_TF32(d, a, b)                                                     \
    asm volatile(                                                             \
        "mma.sync.aligned.m16n8k8.row.col.f32.tf32.tf32.f32 "                 \
        "{%0,%1,%2,%3}, {%4,%5,%6,%7}, {%8,%9}, {%0,%1,%2,%3};"               \
        : "+f"(d[0]), "+f"(d[1]), "+f"(d[2]), "+f"(d[3])                      \
        : "r"(a[0]), "r"(a[1]), "r"(a[2]), "r"(a[3]), "r"(b[0]), "r"(b[1]))

// ------------------------------- TC GEMM core -------------------------------
// C[M=4096, N] = epilogue(A @ B + bias)
// mode: 0 = bias, 1 = swish, 2 = 0.125*(..), 3 = res+, 4 = res + 0.5*
// 128x128 block tile, BK=16, 2-stage cp.async pipeline, 256 thr / 8 warps.
#define AS_STRIDE 20   // [m][k], pad 16->20: frag bank = (4g+tig)%32, all distinct
#define BS_STRIDE 136  // [k][n], pad 128->136: frag bank = (8tig+g)%32, distinct

#define GEMM_LOAD_STAGE(sbuf, kbase)                                           \
    {                                                                          \
        _Pragma("unroll")                                                      \
        for (int it = 0; it < 2; it++) {                                       \
            int idx = tid + it * 256;                                          \
            cp16(&As[sbuf][(idx >> 2) * AS_STRIDE + (idx & 3) * 4],            \
                 &A[(size_t)(m0 + (idx >> 2)) * K + (kbase) + (idx & 3) * 4]); \
            cp16(&Bs[sbuf][(idx >> 5) * BS_STRIDE + (idx & 31) * 4],           \
                 &Bm[(size_t)((kbase) + (idx >> 5)) * N + n0 + (idx & 31) * 4]);\
        }                                                                      \
        asm volatile("cp.async.commit_group;\n");                              \
    }

__device__ __forceinline__ void gemm_core(
    const float* __restrict__ A, const float* __restrict__ Bm,
    const float* __restrict__ bias, const float* __restrict__ res,
    float* __restrict__ C, int N, int K, int mode)
{
    __shared__ float As[2][128 * AS_STRIDE];   // 2 x 10240 B
    __shared__ float Bs[2][16 * BS_STRIDE];    // 2 x  8704 B  (total 37.9 KB)

    const int tid  = threadIdx.x;
    const int lane = tid & 31;
    const int warp = tid >> 5;
    const int g    = lane >> 2;   // groupID 0..7
    const int tig  = lane & 3;    // thread-in-group 0..3

    const int m0 = blockIdx.y * 128;
    const int n0 = blockIdx.x * 128;
    const int wm = (warp & 1) * 64;
    const int wn = (warp >> 1) * 32;

    float acc[4][4][4];
    #pragma unroll
    for (int mt = 0; mt < 4; mt++)
        #pragma unroll
        for (int nt = 0; nt < 4; nt++)
            #pragma unroll
            for (int i = 0; i < 4; i++) acc[mt][nt][i] = 0.0f;

    GEMM_LOAD_STAGE(0, 0);

    const int niter = K >> 4;
    for (int i = 0; i < niter; i++) {
        asm volatile("cp.async.wait_group 0;\n");
        __syncthreads();                       // stage i visible; buf (i+1)&1 free
        if (i + 1 < niter) GEMM_LOAD_STAGE((i + 1) & 1, (i + 1) << 4);

        const float* as = As[i & 1];
        const float* bs = Bs[i & 1];
        #pragma unroll
        for (int ks = 0; ks < 2; ks++) {
            const int kk = ks * 8;
            uint32_t bfrag[4][2];
            #pragma unroll
            for (int nt = 0; nt < 4; nt++) {
                int col = wn + nt * 8 + g;
                bfrag[nt][0] = to_tf32(bs[(kk + tig)     * BS_STRIDE + col]);
                bfrag[nt][1] = to_tf32(bs[(kk + tig + 4) * BS_STRIDE + col]);
            }
            #pragma unroll
            for (int mt = 0; mt < 4; mt++) {
                uint32_t afrag[4];
                int r0 = wm + mt * 16 + g;
                afrag[0] = to_tf32(as[r0       * AS_STRIDE + kk + tig]);
                afrag[1] = to_tf32(as[(r0 + 8) * AS_STRIDE + kk + tig]);
                afrag[2] = to_tf32(as[r0       * AS_STRIDE + kk + tig + 4]);
                afrag[3] = to_tf32(as[(r0 + 8) * AS_STRIDE + kk + tig + 4]);
                #pragma unroll
                for (int nt = 0; nt < 4; nt++)
                    MMA_TF32(acc[mt][nt], afrag, bfrag[nt]);
            }
        }
    }

    // ----------------------------- epilogue ---------------------------------
    #pragma unroll
    for (int mt = 0; mt < 4; mt++) {
        int r0 = m0 + wm + mt * 16 + g;
        #pragma unroll
        for (int nt = 0; nt < 4; nt++) {
            int cb = n0 + wn + nt * 8 + tig * 2;
            float b0 = bias[cb], b1 = bias[cb + 1];
            #pragma unroll
            for (int half = 0; half < 2; half++) {
                int row = r0 + half * 8;
                float c0 = acc[mt][nt][half * 2 + 0] + b0;
                float c1 = acc[mt][nt][half * 2 + 1] + b1;
                if (mode == 1) {
                    c0 = c0 / (1.0f + expf(-c0));
                    c1 = c1 / (1.0f + expf(-c1));
                } else if (mode == 2) {
                    c0 *= 0.125f; c1 *= 0.125f;
                } else if (mode == 3) {
                    const float2 r = *reinterpret_cast<const float2*>(
                        &res[(size_t)row * N + cb]);
                    c0 += r.x; c1 += r.y;
                } else if (mode == 4) {
                    const float2 r = *reinterpret_cast<const float2*>(
                        &res[(size_t)row * N + cb]);
                    c0 = r.x + 0.5f * c0; c1 = r.y + 0.5f * c1;
                }
                float2 o; o.x = c0; o.y = c1;
                *reinterpret_cast<float2*>(&C[(size_t)row * N + cb]) = o;
            }
        }
    }
}

__global__ __launch_bounds__(256, 2)
void gemm_tc(const float* __restrict__ A, const float* __restrict__ Bm,
             const float* __restrict__ bias, const float* __restrict__ res,
             float* __restrict__ C, int N, int K, int mode)
{
    gemm_core(A, Bm, bias, res, C, N, K, mode);
}

// merged QKV: grid.z selects which projection this CTA computes
__global__ __launch_bounds__(256, 2)
void gemm_qkv(const float* __restrict__ A,
              const float* __restrict__ Bq, const float* __restrict__ Bk,
              const float* __restrict__ Bv,
              const float* __restrict__ bq, const float* __restrict__ bk,
              const float* __restrict__ bv,
              float* __restrict__ Cq, float* __restrict__ Ck,
              float* __restrict__ Cv)
{
    int z = blockIdx.z;
    const float* Bm   = (z == 0) ? Bq : (z == 1) ? Bk : Bv;
    const float* bias = (z == 0) ? bq : (z == 1) ? bk : bv;
    float*       C    = (z == 0) ? Cq : (z == 1) ? Ck : Cv;
    gemm_core(A, Bm, bias, nullptr, C, CD, CD, (z == 0) ? 2 : 0);
}

// ------------------------------- Attention ---------------------------------
__global__ void attn_k(const float* __restrict__ q, const float* __restrict__ k,
                       const float* __restrict__ v, const float* __restrict__ hin,
                       float* __restrict__ hout, float* __restrict__ probs)
{
    __shared__ float sc[4][CWB + 1];
    int warp = threadIdx.x >> 5;
    int lane = threadIdx.x & 31;
    int item = blockIdx.x * 4 + warp;          // < B*T*H
    int head = item & (CH - 1);
    int bt   = item >> 3;                      // b*T + t
    int t    = bt & (CT - 1);
    int brow = bt - t;                         // b*T

    const float2* qrow = reinterpret_cast<const float2*>(q + (size_t)bt * CD + head * CDH);
    float2 q2 = qrow[lane];

    for (int w = 0; w < CWB; w++) {
        int tk = t + w - CW1;
        float val = -1e9f;
        if (tk >= 0 && tk < CT) {
            const float2* krow =
                reinterpret_cast<const float2*>(k + (size_t)(brow + tk) * CD + head * CDH);
            float2 k2 = krow[lane];
            float p = q2.x * k2.x + q2.y * k2.y;
            #pragma unroll
            for (int o = 16; o; o >>= 1) p += __shfl_xor_sync(0xffffffffu, p, o);
            val = p;
        }
        if (lane == 0) sc[warp][w] = val;
    }
    __syncwarp();

    float m = -1e30f;
    for (int w = lane; w < CWB; w += 32) m = fmaxf(m, sc[warp][w]);
    #pragma unroll
    for (int o = 16; o; o >>= 1) m = fmaxf(m, __shfl_xor_sync(0xffffffffu, m, o));
    float ssum = 0.0f;
    for (int w = lane; w < CWB; w += 32) {
        float e = expf(sc[warp][w] - m);
        sc[warp][w] = e;
        ssum += e;
    }
    #pragma unroll
    for (int o = 16; o; o >>= 1) ssum += __shfl_xor_sync(0xffffffffu, ssum, o);
    float inv = 1.0f / ssum;
    __syncwarp();

    float* prow = probs + (size_t)item * CWB;
    for (int w = lane; w < CWB; w += 32) {
        float p = sc[warp][w] * inv;
        sc[warp][w] = p;
        prow[w] = p;
    }
    __syncwarp();

    float cx = 0.0f, cy = 0.0f;
    for (int w = 0; w < CWB; w++) {
        int tk = t + w - CW1;
        if (tk < 0 || tk >= CT) continue;
        float p = sc[warp][w];
        const float2* vrow =
            reinterpret_cast<const float2*>(v + (size_t)(brow + tk) * CD + head * CDH);
        float2 v2 = vrow[lane];
        cx = fmaf(p, v2.x, cx);
        cy = fmaf(p, v2.y, cy);
    }
    size_t off = (size_t)bt * CD + head * CDH + lane * 2;
    hout[off]     = hin[off]     + cx;
    hout[off + 1] = hin[off + 1] + cy;
}

// ---------------------------------- GLU ------------------------------------
__global__ void glu_k(const float* __restrict__ in, float* __restrict__ out)
{
    int i = blockIdx.x * 256 + threadIdx.x;    // NTOK*CD threads
    int row = i >> 9;
    int col = i & (CD - 1);
    float a = in[(size_t)row * CCE + col];
    float g = in[(size_t)row * CCE + CD + col];
    out[i] = a / (1.0f + expf(-g));
}

// -------------------- depthwise conv + BN + swish ---------------------------
__global__ void dwconv_k(const float* __restrict__ in, const float* __restrict__ w,
                         const float* __restrict__ dwb, const float* __restrict__ bng,
                         const float* __restrict__ bnb, float* __restrict__ out)
{
    int c  = blockIdx.y * 128 + threadIdx.x;
    int bt = blockIdx.x;
    int t  = bt & (CT - 1);
    int brow = bt - t;

    float acc = 0.0f;
    #pragma unroll
    for (int kk = 0; kk < CKS; kk++) {
        int tt = t + kk - (CKS - 1) / 2;
        if (tt >= 0 && tt < CT)
            acc = fmaf(__ldg(&w[kk * CD + c]),
                       __ldg(&in[(size_t)(brow + tt) * CD + c]), acc);
    }
    acc += dwb[c];
    acc = acc * (rsqrtf(1.0f + CEPS) * bng[c]) + bnb[c];
    out[(size_t)bt * CD + c] = acc / (1.0f + expf(-acc));   // swish
}

// ------------------------------ launch -------------------------------------
extern "C" void kernel_launch(void* const* d_in, const int* in_sizes, int n_in,
                              void* d_out, int out_size)
{
    (void)in_sizes; (void)n_in; (void)out_size;
    const float* x          = (const float*)d_in[0];
    const float* ff1_ln_g   = (const float*)d_in[1];
    const float* ff1_ln_b   = (const float*)d_in[2];
    const float* ff1_w1     = (const float*)d_in[3];
    const float* ff1_b1     = (const float*)d_in[4];
    const float* ff1_w2     = (const float*)d_in[5];
    const float* ff1_b2     = (const float*)d_in[6];
    const float* ff2_ln_g   = (const float*)d_in[7];
    const float* ff2_ln_b   = (const float*)d_in[8];
    const float* ff2_w1     = (const float*)d_in[9];
    const float* ff2_b1     = (const float*)d_in[10];
    const float* ff2_w2     = (const float*)d_in[11];
    const float* ff2_b2     = (const float*)d_in[12];
    const float* wq         = (const float*)d_in[13];
    const float* bq         = (const float*)d_in[14];
    const float* wk         = (const float*)d_in[15];
    const float* bk         = (const float*)d_in[16];
    const float* wv         = (const float*)d_in[17];
    const float* bv         = (const float*)d_in[18];
    const float* conv_ln_g  = (const float*)d_in[19];
    const float* conv_ln_b  = (const float*)d_in[20];
    const float* conv_pw1_w = (const float*)d_in[21];
    const float* conv_pw1_b = (const float*)d_in[22];
    const float* conv_dw_w  = (const float*)d_in[23];
    const float* conv_dw_b  = (const float*)d_in[24];
    const float* conv_bn_g  = (const float*)d_in[25];
    const float* conv_bn_b  = (const float*)d_in[26];
    const float* conv_pw2_w = (const float*)d_in[27];
    const float* conv_pw2_b = (const float*)d_in[28];
    const float* final_ln_g = (const float*)d_in[29];
    const float* final_ln_b = (const float*)d_in[30];

    float* out_main  = (float*)d_out;                         // (B,T,D)
    float* out_probs = (float*)d_out + (size_t)NTOK * CD;     // (B,T,H,WB)

    float *ln_, *ff_, *h_, *h2_, *q_, *k_, *v_, *ce_, *glu_, *dw_;
    cudaGetSymbolAddress((void**)&ln_,  g_ln);
    cudaGetSymbolAddress((void**)&ff_,  g_ff);
    cudaGetSymbolAddress((void**)&h_,   g_h);
    cudaGetSymbolAddress((void**)&h2_,  g_h2);
    cudaGetSymbolAddress((void**)&q_,   g_q);
    cudaGetSymbolAddress((void**)&k_,   g_k);
    cudaGetSymbolAddress((void**)&v_,   g_v);
    cudaGetSymbolAddress((void**)&ce_,  g_ce);
    cudaGetSymbolAddress((void**)&glu_, g_glu);
    cudaGetSymbolAddress((void**)&dw_,  g_dw);

    dim3 blk256(256);
    dim3 gFF1(CFF / 128, NTOK / 128);      // N=2048: 16x32 = 512 CTAs
    dim3 gD  (CD  / 128, NTOK / 128);      // N=512:   4x32 = 128 CTAs
    dim3 gCE (CCE / 128, NTOK / 128);      // N=1024:  8x32 = 256 CTAs
    dim3 gQKV(CD  / 128, NTOK / 128, 3);   // merged QKV: 384 CTAs

    // ---- FF1: h = x + 0.5 * ff(x) ----
    ln_k<<<NTOK, 128>>>(x, ff1_ln_g, ff1_ln_b, ln_);
    gemm_tc<<<gFF1, blk256>>>(ln_, ff1_w1, ff1_b1, nullptr, ff_, CFF, CD, 1);
    gemm_tc<<<gD,   blk256>>>(ff_, ff1_w2, ff1_b2, x,       h_,  CD, CFF, 4);

    // ---- QKV (one launch) ----
    gemm_qkv<<<gQKV, blk256>>>(h_, wq, wk, wv, bq, bk, bv, q_, k_, v_);

    // ---- attention (h2 = h + ctx; probs -> d_out) ----
    attn_k<<<(NTOK * CH) / 4, 128>>>(q_, k_, v_, h_, h2_, out_probs);

    // ---- conv module: h = h2 + conv(h2) ----
    ln_k<<<NTOK, 128>>>(h2_, conv_ln_g, conv_ln_b, ln_);
    gemm_tc<<<gCE, blk256>>>(ln_, conv_pw1_w, conv_pw1_b, nullptr, ce_, CCE, CD, 0);
    glu_k<<<(NTOK * CD) / 256, blk256>>>(ce_, glu_);
    dwconv_k<<<dim3(NTOK, CD / 128), 128>>>(glu_, conv_dw_w, conv_dw_b,
                                            conv_bn_g, conv_bn_b, dw_);
    gemm_tc<<<gD, blk256>>>(dw_, conv_pw2_w, conv_pw2_b, h2_, h_, CD, CD, 3);

    // ---- FF2: h2 = h + 0.5 * ff(h) ----
    ln_k<<<NTOK, 128>>>(h_, ff2_ln_g, ff2_ln_b, ln_);
    gemm_tc<<<gFF1, blk256>>>(ln_, ff2_w1, ff2_b1, nullptr, ff_, CFF, CD, 1);
    gemm_tc<<<gD,   blk256>>>(ff_, ff2_w2, ff2_b2, h_,      h2_, CD, CFF, 4);

    // ---- final LN -> out ----
    ln_k<<<NTOK, 128>>>(h2_, final_ln_g, final_ln_b, out_main);
}